// round 11
// baseline (speedup 1.0000x reference)
#include <cuda_runtime.h>
#include <cstdint>

// SPP: out = concat(x, pool5(x), pool9(x), pool13(x)) along channels.
// pool9 = pool5(pool5(x)), pool13 = pool5(pool9); separable 1-D passes.
// R11: persistent CTAs (grid=888=148*6, grid-stride over planes) with the
//      next plane's input cp.async-prefetched during pool3. Shuffle h-pass,
//      bulk-group stores, L2 policy split (R9/R10 core).
// Buffer roles fixed per iteration: X = input/copy + pool2 scratch,
// Y = pool1 + pool3 scratch. Bulk-group drain chain per plane:
//   pool1 wait<1> drains G_p3(prev)  -> Y free
//   pool2 wait<1> drains G_copy      -> X free
//   pool3 wait<1> drains G_p1        -> Y free
//   pool3 wait<0> drains G_p2        -> X free for prefetch

#define NPLANES   8192      // 16 * 512
#define PLANE_F4  1024      // 64*64 / 4 (64 rows x 16 float4)
#define PLANE_BYTES 16384
#define THREADS   256
#define GRID      888       // 148 SMs * 6 blocks
#define FULL      0xffffffffu

__device__ __forceinline__ uint32_t smem_u32(const void* p) {
    return (uint32_t)__cvta_generic_to_shared(p);
}
__device__ __forceinline__ uint64_t policy_evict_first() {
    uint64_t pol;
    asm volatile("createpolicy.fractional.L2::evict_first.b64 %0, 1.0;" : "=l"(pol));
    return pol;
}
__device__ __forceinline__ void bulk_store_ef(void* gdst, uint32_t ssrc, uint64_t pol) {
    asm volatile(
        "cp.async.bulk.global.shared::cta.bulk_group.L2::cache_hint [%0], [%1], %2, %3;"
        :: "l"(gdst), "r"(ssrc), "n"(PLANE_BYTES), "l"(pol) : "memory");
    asm volatile("cp.async.bulk.commit_group;" ::: "memory");
}
__device__ __forceinline__ void fence_async() {
    asm volatile("fence.proxy.async.shared::cta;" ::: "memory");
}
template <int N>
__device__ __forceinline__ void bulk_wait() {
    asm volatile("cp.async.bulk.wait_group %0;" :: "n"(N) : "memory");
}
__device__ __forceinline__ void cpa16(uint32_t s, const void* g) {
    asm volatile("cp.async.cg.shared.global [%0], [%1], 16;" :: "r"(s), "l"(g) : "memory");
}
__device__ __forceinline__ void cpa_commit() {
    asm volatile("cp.async.commit_group;" ::: "memory");
}
template <int N>
__device__ __forceinline__ void cpa_wait() {
    asm volatile("cp.async.wait_group %0;" :: "n"(N) : "memory");
}

__device__ __forceinline__ float4 v4max(float4 a, float4 b) {
    return make_float4(fmaxf(a.x, b.x), fmaxf(a.y, b.y),
                       fmaxf(a.z, b.z), fmaxf(a.w, b.w));
}

// 5-wide horizontal max using shuffles: window [pz pw | c.x..c.w | nx ny]
__device__ __forceinline__ float4 hmax5_shfl(float4 cu, int xg) {
    const float NEG = __int_as_float(0xff800000);
    float pz = __shfl_up_sync(FULL, cu.z, 1);
    float pw = __shfl_up_sync(FULL, cu.w, 1);
    float nx = __shfl_down_sync(FULL, cu.x, 1);
    float ny = __shfl_down_sync(FULL, cu.y, 1);
    if (xg == 0)  { pz = NEG; pw = NEG; }
    if (xg == 15) { nx = NEG; ny = NEG; }
    float m01 = fmaxf(cu.x, cu.y);
    float m23 = fmaxf(cu.z, cu.w);
    float m0123 = fmaxf(m01, m23);
    float4 o;
    o.x = fmaxf(fmaxf(pz, pw), fmaxf(m01, cu.z));
    o.y = fmaxf(pw, m0123);
    o.z = fmaxf(m0123, nx);
    o.w = fmaxf(fmaxf(cu.y, m23), fmaxf(nx, ny));
    return o;
}

// vertical pass: my 4 h-rows in regs + 2 above + 2 below from scratch S
__device__ __forceinline__ void vpass(const float4* S, const float4 h[4],
                                      float4 v[4], int base, int yg) {
    const float NEG = __int_as_float(0xff800000);
    const float4 NEG4 = make_float4(NEG, NEG, NEG, NEG);
    float4 u0 = (yg > 0)  ? S[base - 32] : NEG4;  // row 4yg-2
    float4 u1 = (yg > 0)  ? S[base - 16] : NEG4;  // row 4yg-1
    float4 d0 = (yg < 15) ? S[base + 64] : NEG4;  // row 4yg+4
    float4 d1 = (yg < 15) ? S[base + 80] : NEG4;  // row 4yg+5
    float4 m12 = v4max(h[1], h[2]);
    v[0] = v4max(v4max(u0, u1), v4max(h[0], m12));
    v[1] = v4max(v4max(u1, h[0]), v4max(m12, h[3]));
    v[2] = v4max(v4max(h[0], m12), v4max(h[3], d0));
    v[3] = v4max(v4max(m12, h[3]), v4max(d0, d1));
}

__global__ __launch_bounds__(THREADS, 6)
void spp_kernel(const float4* __restrict__ in, float4* __restrict__ out) {
    __shared__ float4 X[PLANE_F4];  // input/copy source + pool2 scratch
    __shared__ float4 Y[PLANE_F4];  // pool1 + pool3 scratch

    const int tid = threadIdx.x;
    const int xg = tid & 15;                // float4 column 0..15 (intra-warp)
    const int yg = tid >> 4;                // row-strip 0..15 (rows 4*yg..4*yg+3)
    const int base = ((yg << 2) << 4) + xg; // index of row 4*yg, column xg
    const uint64_t pol_ef = policy_evict_first();

    // ---- prologue: prefetch first plane into X ----
    {
        const float4* s0 = in + (size_t)blockIdx.x * PLANE_F4;
        #pragma unroll
        for (int r = 0; r < 4; r++) {
            int t = base + (r << 4);
            cpa16(smem_u32(&X[t]), &s0[t]);
        }
        cpa_commit();
    }

    for (int p = blockIdx.x; p < NPLANES; p += GRID) {
        const int n = p >> 9;
        const int c = p & 511;
        float4* out0 = out + ((size_t)n * 2048 + c) * PLANE_F4;

        // ---- input landed in X: regs + copy-section store ----
        cpa_wait<0>();
        __syncthreads();
        float4 v[4];
        #pragma unroll
        for (int r = 0; r < 4; r++) v[r] = X[base + (r << 4)];
        if (tid == 0) {
            fence_async();
            bulk_store_ef(out0, smem_u32(X), pol_ef);       // G_copy (reads X)
        }

        float4 h[4];

        // ---- pool 1 (scratch Y) ----
        #pragma unroll
        for (int r = 0; r < 4; r++) h[r] = hmax5_shfl(v[r], xg);
        if (tid == 0) bulk_wait<1>();        // drains G_p3(prev) -> Y free
        __syncthreads();
        #pragma unroll
        for (int r = 0; r < 4; r++) Y[base + (r << 4)] = h[r];
        __syncthreads();
        vpass(Y, h, v, base, yg);
        __syncthreads();
        #pragma unroll
        for (int r = 0; r < 4; r++) Y[base + (r << 4)] = v[r];
        __syncthreads();
        if (tid == 0) {
            fence_async();
            bulk_store_ef(out0 + (size_t)512 * PLANE_F4, smem_u32(Y), pol_ef);  // G_p1
        }

        // ---- pool 2 (scratch X) ----
        #pragma unroll
        for (int r = 0; r < 4; r++) h[r] = hmax5_shfl(v[r], xg);
        if (tid == 0) bulk_wait<1>();        // drains G_copy -> X free
        __syncthreads();
        #pragma unroll
        for (int r = 0; r < 4; r++) X[base + (r << 4)] = h[r];
        __syncthreads();
        vpass(X, h, v, base, yg);
        __syncthreads();
        #pragma unroll
        for (int r = 0; r < 4; r++) X[base + (r << 4)] = v[r];
        __syncthreads();
        if (tid == 0) {
            fence_async();
            bulk_store_ef(out0 + (size_t)1024 * PLANE_F4, smem_u32(X), pol_ef); // G_p2
        }

        // ---- pool 3 (scratch Y) + prefetch next plane into X ----
        #pragma unroll
        for (int r = 0; r < 4; r++) h[r] = hmax5_shfl(v[r], xg);
        if (tid == 0) bulk_wait<1>();        // drains G_p1 -> Y free
        __syncthreads();
        #pragma unroll
        for (int r = 0; r < 4; r++) Y[base + (r << 4)] = h[r];
        if (tid == 0) bulk_wait<0>();        // drains G_p2 -> X free for prefetch
        __syncthreads();                     // h visible AND X-drain visible
        const int pn = p + GRID;
        if (pn < NPLANES) {
            const float4* sn = in + (size_t)pn * PLANE_F4;
            #pragma unroll
            for (int r = 0; r < 4; r++) {
                int t = base + (r << 4);
                cpa16(smem_u32(&X[t]), &sn[t]);
            }
            cpa_commit();
        }
        vpass(Y, h, v, base, yg);
        __syncthreads();
        #pragma unroll
        for (int r = 0; r < 4; r++) Y[base + (r << 4)] = v[r];
        __syncthreads();
        if (tid == 0) {
            fence_async();
            bulk_store_ef(out0 + (size_t)1536 * PLANE_F4, smem_u32(Y), pol_ef); // G_p3
        }
    }

    // drain remaining bulk stores before CTA exit
    if (tid == 0) bulk_wait<0>();
}

extern "C" void kernel_launch(void* const* d_in, const int* in_sizes, int n_in,
                              void* d_out, int out_size) {
    const float4* x = (const float4*)d_in[0];
    float4* out = (float4*)d_out;
    spp_kernel<<<GRID, THREADS>>>(x, out);
}

// round 12
// speedup vs baseline: 1.1217x; 1.1217x over previous
#include <cuda_runtime.h>
#include <cstdint>

// SPP: out = concat(x, pool5(x), pool9(x), pool13(x)) along channels.
// pool9 = pool5(pool5(x)), pool13 = pool5(pool9); separable 1-D passes.
// R12 = R10 (shuffle h-pass, bulk-group stores, L2 policy split, 6 blocks/SM)
//       + first-wave phase stagger: under graph replay all resident blocks run
//       in lockstep, so 16KB store bursts align chip-wide and DRAM oscillates
//       between idle (compute phases) and backpressure (store floods).
//       Stagger wave-1 block starts by 0..~2us; later waves inherit the skew.

#define NPLANES   8192      // 16 * 512
#define PLANE_F4  1024      // 64*64 / 4 (64 rows x 16 float4)
#define PLANE_BYTES 16384
#define THREADS   256
#define WAVE      888       // 148 SMs * 6 blocks resident
#define FULL      0xffffffffu

__device__ __forceinline__ uint32_t smem_u32(const void* p) {
    return (uint32_t)__cvta_generic_to_shared(p);
}
__device__ __forceinline__ uint64_t policy_evict_first() {
    uint64_t pol;
    asm volatile("createpolicy.fractional.L2::evict_first.b64 %0, 1.0;" : "=l"(pol));
    return pol;
}
__device__ __forceinline__ uint64_t policy_evict_last() {
    uint64_t pol;
    asm volatile("createpolicy.fractional.L2::evict_last.b64 %0, 1.0;" : "=l"(pol));
    return pol;
}
__device__ __forceinline__ void bulk_store_ef(void* gdst, uint32_t ssrc, uint64_t pol) {
    asm volatile(
        "cp.async.bulk.global.shared::cta.bulk_group.L2::cache_hint [%0], [%1], %2, %3;"
        :: "l"(gdst), "r"(ssrc), "n"(PLANE_BYTES), "l"(pol) : "memory");
    asm volatile("cp.async.bulk.commit_group;" ::: "memory");
}
__device__ __forceinline__ void fence_async() {
    asm volatile("fence.proxy.async.shared::cta;" ::: "memory");
}
template <int N>
__device__ __forceinline__ void bulk_wait() {
    asm volatile("cp.async.bulk.wait_group %0;" :: "n"(N) : "memory");
}
__device__ __forceinline__ float4 ldg_evict_last(const float4* p, uint64_t pol) {
    float4 v;
    asm volatile("ld.global.L2::cache_hint.v4.f32 {%0,%1,%2,%3}, [%4], %5;"
                 : "=f"(v.x), "=f"(v.y), "=f"(v.z), "=f"(v.w)
                 : "l"(p), "l"(pol));
    return v;
}

__device__ __forceinline__ float4 v4max(float4 a, float4 b) {
    return make_float4(fmaxf(a.x, b.x), fmaxf(a.y, b.y),
                       fmaxf(a.z, b.z), fmaxf(a.w, b.w));
}

// 5-wide horizontal max using shuffles: window [pz pw | c.x..c.w | nx ny]
__device__ __forceinline__ float4 hmax5_shfl(float4 cu, int xg) {
    const float NEG = __int_as_float(0xff800000);
    float pz = __shfl_up_sync(FULL, cu.z, 1);
    float pw = __shfl_up_sync(FULL, cu.w, 1);
    float nx = __shfl_down_sync(FULL, cu.x, 1);
    float ny = __shfl_down_sync(FULL, cu.y, 1);
    if (xg == 0)  { pz = NEG; pw = NEG; }
    if (xg == 15) { nx = NEG; ny = NEG; }
    float m01 = fmaxf(cu.x, cu.y);
    float m23 = fmaxf(cu.z, cu.w);
    float m0123 = fmaxf(m01, m23);
    float4 o;
    o.x = fmaxf(fmaxf(pz, pw), fmaxf(m01, cu.z));
    o.y = fmaxf(pw, m0123);
    o.z = fmaxf(m0123, nx);
    o.w = fmaxf(fmaxf(cu.y, m23), fmaxf(nx, ny));
    return o;
}

__global__ __launch_bounds__(THREADS, 6)
void spp_kernel(const float4* __restrict__ in, float4* __restrict__ out) {
    __shared__ float4 S0[PLANE_F4];
    __shared__ float4 S1[PLANE_F4];

    const float NEG = __int_as_float(0xff800000);  // -inf
    const float4 NEG4 = make_float4(NEG, NEG, NEG, NEG);

    const int plane = blockIdx.x;           // n*512 + c
    const int n = plane >> 9;
    const int c = plane & 511;
    const int tid = threadIdx.x;
    const int xg = tid & 15;                // float4 column 0..15 (intra-warp)
    const int yg = tid >> 4;                // row-strip 0..15 (rows 4*yg..4*yg+3)
    const int base = ((yg << 2) << 4) + xg; // index of row 4*yg, column xg

    // ---- first-wave phase stagger: decorrelate store bursts chip-wide ----
    if (plane < WAVE) {
        unsigned slot = plane % 6u;         // 6 co-resident blocks per SM
        if (slot) __nanosleep(slot * 350u); // 0 .. 1.75us skew
    }

    const float4* src = in + (size_t)plane * PLANE_F4;
    float4* out0 = out + ((size_t)n * 2048 + c) * PLANE_F4;

    const uint64_t pol_ef = policy_evict_first();
    const uint64_t pol_el = policy_evict_last();

    // ---- load strip into regs + S0; copy section via bulk store from S0 ----
    float4 v[4];
    #pragma unroll
    for (int r = 0; r < 4; r++) {
        int t = base + (r << 4);
        v[r] = ldg_evict_last(&src[t], pol_el);
        S0[t] = v[r];
    }
    __syncthreads();
    if (tid == 0) {
        fence_async();
        bulk_store_ef(out0, smem_u32(S0), pol_ef);   // W_copy (reads S0)
    }

    float4* cur = S0;   // source of most recent pending bulk store
    float4* nxt = S1;   // scratch for this pool (h-exchange, then v / bulk src)

    // ---- three cascaded pool5 stages ----
    #pragma unroll
    for (int pool = 0; pool < 3; pool++) {
        // horizontal pass: pure register/shuffle, no smem
        float4 h[4];
        #pragma unroll
        for (int r = 0; r < 4; r++) h[r] = hmax5_shfl(v[r], xg);

        // before overwriting nxt: its previous bulk store (2 groups back) done
        if (tid == 0) bulk_wait<1>();
        __syncthreads();
        #pragma unroll
        for (int r = 0; r < 4; r++) nxt[base + (r << 4)] = h[r];
        __syncthreads();

        // vertical pass: my 4 h-rows in regs + 2 above + 2 below from nxt
        float4 u0 = (yg > 0)  ? nxt[base - 32] : NEG4;  // row 4yg-2
        float4 u1 = (yg > 0)  ? nxt[base - 16] : NEG4;  // row 4yg-1
        float4 d0 = (yg < 15) ? nxt[base + 64] : NEG4;  // row 4yg+4
        float4 d1 = (yg < 15) ? nxt[base + 80] : NEG4;  // row 4yg+5

        float4 m12 = v4max(h[1], h[2]);                 // shared subexpression
        v[0] = v4max(v4max(u0, u1), v4max(h[0], m12));
        v[1] = v4max(v4max(u1, h[0]), v4max(m12, h[3]));
        v[2] = v4max(v4max(h[0], m12), v4max(h[3], d0));
        v[3] = v4max(v4max(m12, h[3]), v4max(d0, d1));

        __syncthreads();                    // all v-pass reads of nxt done
        #pragma unroll
        for (int r = 0; r < 4; r++) nxt[base + (r << 4)] = v[r];
        __syncthreads();                    // v-plane complete in nxt
        if (tid == 0) {
            fence_async();
            bulk_store_ef(out0 + (size_t)(pool + 1) * 512 * PLANE_F4,
                          smem_u32(nxt), pol_ef);
        }
        // swap: nxt becomes the pending-store buffer; old cur is reusable
        float4* tmp = cur; cur = nxt; nxt = tmp;
    }

    // drain remaining bulk stores before CTA exit
    if (tid == 0) bulk_wait<0>();
}

extern "C" void kernel_launch(void* const* d_in, const int* in_sizes, int n_in,
                              void* d_out, int out_size) {
    const float4* x = (const float4*)d_in[0];
    float4* out = (float4*)d_out;
    spp_kernel<<<NPLANES, THREADS>>>(x, out);
}